// round 1
// baseline (speedup 1.0000x reference)
#include <cuda_runtime.h>
#include <math.h>

#define T_TOK 4096
#define EMB   1024
#define NEXP  8
#define HID   2048
#define CAP   4096   // max tokens per expert (top-2 of 8, experts distinct per token)

// ---------------- device scratch (static: no allocations allowed) -----------
__device__ int   g_counts[NEXP];
__device__ int   g_toks [NEXP * CAP];
__device__ float g_gates[NEXP * CAP];
__device__ float g_h1[(size_t)NEXP * CAP * HID];   // 256 MB
__device__ float g_h2[(size_t)NEXP * CAP * HID];   // 256 MB

// ---------------- init ------------------------------------------------------
__global__ void init_counts_kernel() {
    if (threadIdx.x < NEXP) g_counts[threadIdx.x] = 0;
}

// ---------------- router: one warp per token --------------------------------
__global__ void router_kernel(const float* __restrict__ x,
                              const float* __restrict__ Wr,
                              const float* __restrict__ br)
{
    int warp = (blockIdx.x * blockDim.x + threadIdx.x) >> 5;
    int lane = threadIdx.x & 31;
    if (warp >= T_TOK) return;

    const float* xr = x + (size_t)warp * EMB;
    float acc[NEXP];
#pragma unroll
    for (int e = 0; e < NEXP; e++) acc[e] = 0.f;

    for (int i = lane; i < EMB; i += 32) {
        float xv = xr[i];
        const float* wrow = Wr + i * NEXP;
#pragma unroll
        for (int e = 0; e < NEXP; e++) acc[e] += xv * wrow[e];
    }
#pragma unroll
    for (int off = 16; off; off >>= 1) {
#pragma unroll
        for (int e = 0; e < NEXP; e++)
            acc[e] += __shfl_xor_sync(0xffffffffu, acc[e], off);
    }

    if (lane == 0) {
        float l[NEXP], p[NEXP];
        float mx = -1e30f;
#pragma unroll
        for (int e = 0; e < NEXP; e++) { l[e] = acc[e] + br[e]; mx = fmaxf(mx, l[e]); }
        float s = 0.f;
#pragma unroll
        for (int e = 0; e < NEXP; e++) { p[e] = expf(l[e] - mx); s += p[e]; }
        float inv = 1.f / s;

        // top-1 (lowest index wins ties, matching jax.lax.top_k)
        int i1 = 0;
#pragma unroll
        for (int e = 1; e < NEXP; e++) if (p[e] > p[i1]) i1 = e;
        // top-2
        int i2 = (i1 == 0) ? 1 : 0;
#pragma unroll
        for (int e = 0; e < NEXP; e++) if (e != i1 && p[e] > p[i2]) i2 = e;

        int pos = atomicAdd(&g_counts[i1], 1);
        g_toks [i1 * CAP + pos] = warp;
        g_gates[i1 * CAP + pos] = p[i1] * inv;
        pos = atomicAdd(&g_counts[i2], 1);
        g_toks [i2 * CAP + pos] = warp;
        g_gates[i2 * CAP + pos] = p[i2] * inv;
    }
}

// ---------------- grouped SGEMM ---------------------------------------------
// MODE 0: h1 = gather(x) @ W1[e] + b1[e]               (A = x via token gather)
// MODE 1: h2 = relu(h1 @ Wg[e] + bg[e])
// MODE 2: out[token] += gate * (h2 @ W2[e] + b2[e])    (atomic scatter)
// Tiles: 64x64, BK=16, 256 threads, 4x4 per-thread.
template<int MODE, int N, int K>
__global__ __launch_bounds__(256)
void gemm_kernel(const float* __restrict__ Aext,
                 const float* __restrict__ B,
                 const float* __restrict__ bias,
                 float* __restrict__ out)
{
    const int e   = blockIdx.z;
    const int cnt = g_counts[e];
    const int m0  = blockIdx.y * 64;
    if (m0 >= cnt) return;                       // over-provisioned tile: exit
    const int n0  = blockIdx.x * 64;

    __shared__ float As[16][64];
    __shared__ float Bs[16][64];

    const int tid  = threadIdx.x;
    const int arow = tid >> 2;            // 0..63
    const int acol = (tid & 3) << 2;      // 0,4,8,12
    const int brow = tid >> 4;            // 0..15
    const int bcol = (tid & 15) << 2;     // 0..60
    const int tx   = tid & 15;
    const int ty   = tid >> 4;

    const float* __restrict__ Bp = B + (size_t)e * K * N + n0 + bcol;

    // A source pointer (row stride == K in all modes)
    const float* Ap = nullptr;
    if (MODE == 0) {
        if (m0 + arow < cnt)
            Ap = Aext + (size_t)g_toks[e * CAP + m0 + arow] * K + acol;
    } else {
        const float* Abuf = (MODE == 1) ? g_h1 : g_h2;
        Ap = Abuf + (size_t)(e * CAP + m0 + arow) * K + acol;
    }

    float acc[4][4];
#pragma unroll
    for (int i = 0; i < 4; i++)
#pragma unroll
        for (int j = 0; j < 4; j++) acc[i][j] = 0.f;

    for (int k0 = 0; k0 < K; k0 += 16) {
        float4 av = make_float4(0.f, 0.f, 0.f, 0.f);
        if (Ap) av = *(const float4*)(Ap + k0);
        As[acol + 0][arow] = av.x;
        As[acol + 1][arow] = av.y;
        As[acol + 2][arow] = av.z;
        As[acol + 3][arow] = av.w;

        float4 bv = *(const float4*)(Bp + (size_t)(k0 + brow) * N);
        *(float4*)&Bs[brow][bcol] = bv;
        __syncthreads();

#pragma unroll
        for (int k = 0; k < 16; k++) {
            float4 a4 = *(const float4*)&As[k][ty << 2];
            float4 b4 = *(const float4*)&Bs[k][tx << 2];
            float ar[4] = {a4.x, a4.y, a4.z, a4.w};
            float bb[4] = {b4.x, b4.y, b4.z, b4.w};
#pragma unroll
            for (int i = 0; i < 4; i++)
#pragma unroll
                for (int j = 0; j < 4; j++)
                    acc[i][j] += ar[i] * bb[j];
        }
        __syncthreads();
    }

    // ---------------- epilogue ----------------
    if (MODE == 2) {
#pragma unroll
        for (int i = 0; i < 4; i++) {
            int r = m0 + (ty << 2) + i;
            if (r < cnt) {
                int   token = g_toks [e * CAP + r];
                float gv    = g_gates[e * CAP + r];
                float*       op = out  + (size_t)token * N + n0 + (tx << 2);
                const float* bp = bias + (size_t)e * N + n0 + (tx << 2);
#pragma unroll
                for (int j = 0; j < 4; j++)
                    atomicAdd(op + j, gv * (acc[i][j] + bp[j]));
            }
        }
    } else {
        float* Cbuf = (MODE == 0) ? g_h1 : g_h2;
#pragma unroll
        for (int i = 0; i < 4; i++) {
            float*       cp = Cbuf + (size_t)(e * CAP + m0 + (ty << 2) + i) * N + n0 + (tx << 2);
            const float* bp = bias + (size_t)e * N + n0 + (tx << 2);
#pragma unroll
            for (int j = 0; j < 4; j++) {
                float v = acc[i][j] + bp[j];
                if (MODE == 1) v = fmaxf(v, 0.f);
                cp[j] = v;
            }
        }
    }
}

// ---------------- launch -----------------------------------------------------
extern "C" void kernel_launch(void* const* d_in, const int* in_sizes, int n_in,
                              void* d_out, int out_size)
{
    const float* x  = (const float*)d_in[0];
    const float* Wr = (const float*)d_in[1];
    const float* br = (const float*)d_in[2];
    const float* W1 = (const float*)d_in[3];
    const float* b1 = (const float*)d_in[4];
    const float* Wg = (const float*)d_in[5];
    const float* bg = (const float*)d_in[6];
    const float* W2 = (const float*)d_in[7];
    const float* b2 = (const float*)d_in[8];
    float* out = (float*)d_out;

    cudaMemsetAsync(out, 0, (size_t)T_TOK * EMB * sizeof(float));
    init_counts_kernel<<<1, 32>>>();
    router_kernel<<<(T_TOK * 32 + 255) / 256, 256>>>(x, Wr, br);

    dim3 blk(256);
    gemm_kernel<0, HID, EMB><<<dim3(HID / 64, CAP / 64, NEXP), blk>>>(x,       W1, b1, nullptr);
    gemm_kernel<1, HID, HID><<<dim3(HID / 64, CAP / 64, NEXP), blk>>>(nullptr, Wg, bg, nullptr);
    gemm_kernel<2, EMB, HID><<<dim3(EMB / 64, CAP / 64, NEXP), blk>>>(nullptr, W2, b2, out);
}

// round 3
// speedup vs baseline: 2.7878x; 2.7878x over previous
#include <cuda_runtime.h>
#include <math.h>
#include <stdint.h>

#define T_TOK 4096
#define EMB   1024
#define NEXP  8
#define HID   2048
#define CAP   4096

#define BM 128
#define BN 128
#define BK 16
#define ASTRIDE 20    // floats; (20*r + c) % 32 distinct for r<8,c<4 -> conflict-free A frags
#define BSTRIDE 136   // floats; (8*k + n) % 32 distinct for k<4,n<8 -> conflict-free B frags

// ---------------- device scratch (no allocations allowed) -------------------
__device__ int   g_counts[NEXP];
__device__ int   g_toks [NEXP * CAP];
__device__ float g_gates[NEXP * CAP];
__device__ float g_h1[(size_t)NEXP * CAP * HID];
__device__ float g_h2[(size_t)NEXP * CAP * HID];
__device__ float g_w1t[(size_t)NEXP * EMB * HID];
__device__ float g_wgt[(size_t)NEXP * HID * HID];
__device__ float g_w2t[(size_t)NEXP * HID * EMB];
__device__ float g_xt [(size_t)T_TOK * EMB];

// ---------------- helpers ----------------------------------------------------
__device__ __forceinline__ float to_tf32(float f) {
    uint32_t u;
    asm("cvt.rna.tf32.f32 %0, %1;" : "=r"(u) : "f"(f));
    return __uint_as_float(u);
}
__device__ __forceinline__ void cp16(uint32_t dst, const void* src) {
    asm volatile("cp.async.cg.shared.global [%0], [%1], 16;\n" :: "r"(dst), "l"(src));
}

// ---------------- init ------------------------------------------------------
__global__ void init_counts_kernel() {
    if (threadIdx.x < NEXP) g_counts[threadIdx.x] = 0;
}

// ---------------- tf32 pre-round (RNA) ---------------------------------------
__global__ void tf32_convert_kernel(const float* __restrict__ src,
                                    float* __restrict__ dst, int n4)
{
    int i = blockIdx.x * blockDim.x + threadIdx.x;
    if (i < n4) {
        float4 v = ((const float4*)src)[i];
        v.x = to_tf32(v.x); v.y = to_tf32(v.y);
        v.z = to_tf32(v.z); v.w = to_tf32(v.w);
        ((float4*)dst)[i] = v;
    }
}

// ---------------- router: one warp per token --------------------------------
__global__ void router_kernel(const float* __restrict__ x,
                              const float* __restrict__ Wr,
                              const float* __restrict__ br)
{
    int warp = (blockIdx.x * blockDim.x + threadIdx.x) >> 5;
    int lane = threadIdx.x & 31;
    if (warp >= T_TOK) return;

    const float* xr = x + (size_t)warp * EMB;
    float acc[NEXP];
#pragma unroll
    for (int e = 0; e < NEXP; e++) acc[e] = 0.f;
    for (int i = lane; i < EMB; i += 32) {
        float xv = xr[i];
        const float* wrow = Wr + i * NEXP;
#pragma unroll
        for (int e = 0; e < NEXP; e++) acc[e] += xv * wrow[e];
    }
#pragma unroll
    for (int off = 16; off; off >>= 1)
#pragma unroll
        for (int e = 0; e < NEXP; e++)
            acc[e] += __shfl_xor_sync(0xffffffffu, acc[e], off);

    if (lane == 0) {
        float l[NEXP], p[NEXP];
        float mx = -1e30f;
#pragma unroll
        for (int e = 0; e < NEXP; e++) { l[e] = acc[e] + br[e]; mx = fmaxf(mx, l[e]); }
        float s = 0.f;
#pragma unroll
        for (int e = 0; e < NEXP; e++) { p[e] = expf(l[e] - mx); s += p[e]; }
        float inv = 1.f / s;

        int i1 = 0;
#pragma unroll
        for (int e = 1; e < NEXP; e++) if (p[e] > p[i1]) i1 = e;
        int i2 = (i1 == 0) ? 1 : 0;
#pragma unroll
        for (int e = 0; e < NEXP; e++) if (e != i1 && p[e] > p[i2]) i2 = e;

        int pos = atomicAdd(&g_counts[i1], 1);
        g_toks [i1 * CAP + pos] = warp;
        g_gates[i1 * CAP + pos] = p[i1] * inv;
        pos = atomicAdd(&g_counts[i2], 1);
        g_toks [i2 * CAP + pos] = warp;
        g_gates[i2 * CAP + pos] = p[i2] * inv;
    }
}

// ---------------- grouped TF32 tensor-core GEMM ------------------------------
// MODE 0: h1 = gather(x_tf) @ W1t[e] + b1[e]            -> tf32-rounded store
// MODE 1: h2 = relu(h1 @ Wgt[e] + bg[e])                -> tf32-rounded store
// MODE 2: out[token] += gate * (h2 @ W2t[e] + b2[e])    -> fp32 atomic scatter
template<int MODE, int N, int K>
__global__ __launch_bounds__(256, 1)
void mma_gemm_kernel(const float* __restrict__ Aext,
                     const float* __restrict__ B,
                     const float* __restrict__ bias,
                     float* __restrict__ out)
{
    const int e   = blockIdx.z;
    const int cnt = g_counts[e];
    const int m0  = blockIdx.y * BM;
    if (m0 >= cnt) return;
    const int n0  = blockIdx.x * BN;

    __shared__ float As[2][BM][ASTRIDE];   // 20480 B
    __shared__ float Bs[2][BK][BSTRIDE];   // 17408 B

    const int tid  = threadIdx.x;
    const int lane = tid & 31;
    const int w    = tid >> 5;
    const int wm   = (w & 1) * 64;     // 2 warps in M
    const int wn   = (w >> 1) * 32;    // 4 warps in N
    const int lr   = lane >> 2;        // 0..7
    const int lc   = lane & 3;         // 0..3

    // ---- A cp.async source: 2 chunks (rows am, am+64), 16B each ----
    const int am  = tid >> 2;          // 0..63
    const int akq = (tid & 3) * 4;     // 0,4,8,12
    const float* arow0;
    const float* arow1;
    if (MODE == 0) {
        int r0 = m0 + am;      r0 = r0 < cnt ? r0 : cnt - 1;
        int r1 = m0 + am + 64; r1 = r1 < cnt ? r1 : cnt - 1;
        arow0 = Aext + (size_t)g_toks[e * CAP + r0] * K + akq;
        arow1 = Aext + (size_t)g_toks[e * CAP + r1] * K + akq;
    } else {
        const float* Ab = (MODE == 1) ? g_h1 : g_h2;
        arow0 = Ab + (size_t)(e * CAP + m0 + am) * K + akq;
        arow1 = arow0 + (size_t)64 * K;
    }
    // ---- B cp.async source: 2 chunks (k rows bk, bk+8) ----
    const int bk  = tid >> 5;          // 0..7
    const int bnq = (tid & 31) * 4;    // 0..124
    const float* bsrc = B + (size_t)e * K * N + (size_t)bk * N + n0 + bnq;

    const uint32_t sA0 = (uint32_t)__cvta_generic_to_shared(&As[0][am][akq]);
    const uint32_t sA1 = (uint32_t)__cvta_generic_to_shared(&As[0][am + 64][akq]);
    const uint32_t sB0 = (uint32_t)__cvta_generic_to_shared(&Bs[0][bk][bnq]);
    const uint32_t sB1 = (uint32_t)__cvta_generic_to_shared(&Bs[0][bk + 8][bnq]);
    const uint32_t aSz = sizeof(float) * BM * ASTRIDE;
    const uint32_t bSz = sizeof(float) * BK * BSTRIDE;

    float acc[4][4][4];
#pragma unroll
    for (int i = 0; i < 4; i++)
#pragma unroll
        for (int j = 0; j < 4; j++)
#pragma unroll
            for (int q = 0; q < 4; q++) acc[i][j][q] = 0.f;

    auto load_stage = [&](int buf, int k0) {
        uint32_t ao = buf ? aSz : 0u, bo = buf ? bSz : 0u;
        cp16(sA0 + ao, arow0 + k0);
        cp16(sA1 + ao, arow1 + k0);
        cp16(sB0 + bo, bsrc + (size_t)k0 * N);
        cp16(sB1 + bo, bsrc + (size_t)(k0 + 8) * N);
    };

    load_stage(0, 0);
    asm volatile("cp.async.commit_group;\n" ::: "memory");

    const int ITERS = K / BK;
    for (int it = 0; it < ITERS; it++) {
        if (it + 1 < ITERS) load_stage((it + 1) & 1, (it + 1) * BK);
        asm volatile("cp.async.commit_group;\n" ::: "memory");
        asm volatile("cp.async.wait_group 1;\n" ::: "memory");
        __syncthreads();
        const int b = it & 1;
#pragma unroll
        for (int kc = 0; kc < BK; kc += 8) {
            uint32_t af[4][4], bf[4][2];
#pragma unroll
            for (int i = 0; i < 4; i++) {
                int m = wm + i * 16 + lr;
                af[i][0] = __float_as_uint(As[b][m    ][kc + lc]);
                af[i][1] = __float_as_uint(As[b][m + 8][kc + lc]);
                af[i][2] = __float_as_uint(As[b][m    ][kc + lc + 4]);
                af[i][3] = __float_as_uint(As[b][m + 8][kc + lc + 4]);
            }
#pragma unroll
            for (int j = 0; j < 4; j++) {
                int n = wn + j * 8 + lr;
                bf[j][0] = __float_as_uint(Bs[b][kc + lc    ][n]);
                bf[j][1] = __float_as_uint(Bs[b][kc + lc + 4][n]);
            }
#pragma unroll
            for (int i = 0; i < 4; i++)
#pragma unroll
                for (int j = 0; j < 4; j++) {
                    asm volatile(
                        "mma.sync.aligned.m16n8k8.row.col.f32.tf32.tf32.f32 "
                        "{%0,%1,%2,%3}, {%4,%5,%6,%7}, {%8,%9}, {%0,%1,%2,%3};\n"
                        : "+f"(acc[i][j][0]), "+f"(acc[i][j][1]),
                          "+f"(acc[i][j][2]), "+f"(acc[i][j][3])
                        : "r"(af[i][0]), "r"(af[i][1]), "r"(af[i][2]), "r"(af[i][3]),
                          "r"(bf[j][0]), "r"(bf[j][1]));
                }
        }
        __syncthreads();
    }

    // ---------------- epilogue ----------------
    const float* bp = bias + (size_t)e * N;
    if (MODE == 2) {
#pragma unroll
        for (int i = 0; i < 4; i++)
#pragma unroll
            for (int half = 0; half < 2; half++) {
                int r = m0 + wm + i * 16 + lr + half * 8;
                if (r < cnt) {
                    int   tok = g_toks [e * CAP + r];
                    float gv  = g_gates[e * CAP + r];
#pragma unroll
                    for (int j = 0; j < 4; j++) {
                        int n = n0 + wn + j * 8 + lc * 2;
                        float v0 = acc[i][j][half * 2 + 0] + bp[n];
                        float v1 = acc[i][j][half * 2 + 1] + bp[n + 1];
                        atomicAdd(out + (size_t)tok * N + n,     gv * v0);
                        atomicAdd(out + (size_t)tok * N + n + 1, gv * v1);
                    }
                }
            }
    } else {
        float* Cb = (MODE == 0) ? g_h1 : g_h2;
#pragma unroll
        for (int i = 0; i < 4; i++)
#pragma unroll
            for (int half = 0; half < 2; half++) {
                int r = m0 + wm + i * 16 + lr + half * 8;
                float* crow = Cb + (size_t)(e * CAP + r) * N;
#pragma unroll
                for (int j = 0; j < 4; j++) {
                    int n = n0 + wn + j * 8 + lc * 2;
                    float v0 = acc[i][j][half * 2 + 0] + bp[n];
                    float v1 = acc[i][j][half * 2 + 1] + bp[n + 1];
                    if (MODE == 1) { v0 = fmaxf(v0, 0.f); v1 = fmaxf(v1, 0.f); }
                    float2 st = make_float2(to_tf32(v0), to_tf32(v1));
                    *(float2*)(crow + n) = st;
                }
            }
    }
}

// ---------------- launch -----------------------------------------------------
extern "C" void kernel_launch(void* const* d_in, const int* in_sizes, int n_in,
                              void* d_out, int out_size)
{
    const float* x  = (const float*)d_in[0];
    const float* Wr = (const float*)d_in[1];
    const float* br = (const float*)d_in[2];
    const float* W1 = (const float*)d_in[3];
    const float* b1 = (const float*)d_in[4];
    const float* Wg = (const float*)d_in[5];
    const float* bg = (const float*)d_in[6];
    const float* W2 = (const float*)d_in[7];
    const float* b2 = (const float*)d_in[8];
    float* out = (float*)d_out;

    float *p_x, *p_w1, *p_wg, *p_w2;
    cudaGetSymbolAddress((void**)&p_x,  g_xt);
    cudaGetSymbolAddress((void**)&p_w1, g_w1t);
    cudaGetSymbolAddress((void**)&p_wg, g_wgt);
    cudaGetSymbolAddress((void**)&p_w2, g_w2t);

    cudaMemsetAsync(out, 0, (size_t)T_TOK * EMB * sizeof(float));
    init_counts_kernel<<<1, 32>>>();
    router_kernel<<<(T_TOK * 32 + 255) / 256, 256>>>(x, Wr, br);

    {   // RNA-round inputs/weights to tf32
        int n4;
        n4 = T_TOK * EMB / 4;
        tf32_convert_kernel<<<(n4 + 255) / 256, 256>>>(x, p_x, n4);
        n4 = NEXP * EMB * HID / 4;
        tf32_convert_kernel<<<(n4 + 255) / 256, 256>>>(W1, p_w1, n4);
        n4 = NEXP * HID * HID / 4;
        tf32_convert_kernel<<<(n4 + 255) / 256, 256>>>(Wg, p_wg, n4);
        n4 = NEXP * HID * EMB / 4;
        tf32_convert_kernel<<<(n4 + 255) / 256, 256>>>(W2, p_w2, n4);
    }

    dim3 blk(256);
    mma_gemm_kernel<0, HID, EMB><<<dim3(HID / BN, CAP / BM, NEXP), blk>>>(p_x,     p_w1, b1, nullptr);
    mma_gemm_kernel<1, HID, HID><<<dim3(HID / BN, CAP / BM, NEXP), blk>>>(nullptr, p_wg, bg, nullptr);
    mma_gemm_kernel<2, EMB, HID><<<dim3(EMB / BN, CAP / BM, NEXP), blk>>>(nullptr, p_w2, b2, out);
}

// round 4
// speedup vs baseline: 5.0184x; 1.8001x over previous
#include <cuda_runtime.h>
#include <cuda_fp16.h>
#include <math.h>
#include <stdint.h>

#define T_TOK 4096
#define EMB   1024
#define NEXP  8
#define HID   2048
#define CAP   4096

#define BM 128
#define BN 128
#define BK 32
#define SA 40     // halves per A smem row: b32 stride 20 -> bank (20*gr+lc)%32 all-distinct
#define SB 272    // halves per B smem row: b32 stride 136 -> bank (8*kp+n)%32 all-distinct

// ---------------- device scratch (no allocations allowed) -------------------
__device__ int    g_counts[NEXP];
__device__ int    g_toks [NEXP * CAP];
__device__ float  g_gates[NEXP * CAP];
__device__ __half g_h1 [(size_t)NEXP * CAP * HID];
__device__ __half g_h2 [(size_t)NEXP * CAP * HID];
__device__ __half g_w1h[(size_t)NEXP * EMB * HID];
__device__ __half g_wgh[(size_t)NEXP * HID * HID];
__device__ __half g_w2h[(size_t)NEXP * HID * EMB];
__device__ __half g_xh [(size_t)T_TOK * EMB];

// ---------------- helpers ----------------------------------------------------
__device__ __forceinline__ void cp16(uint32_t dst, const void* src) {
    asm volatile("cp.async.cg.shared.global [%0], [%1], 16;\n" :: "r"(dst), "l"(src));
}

// ---------------- init ------------------------------------------------------
__global__ void init_counts_kernel() {
    if (threadIdx.x < NEXP) g_counts[threadIdx.x] = 0;
}

// ---------------- fp32 -> fp16 elementwise (for x) ---------------------------
__global__ void xh_convert_kernel(const float* __restrict__ src,
                                  __half* __restrict__ dst, int n4)
{
    int i = blockIdx.x * blockDim.x + threadIdx.x;
    if (i < n4) {
        float4 v = ((const float4*)src)[i];
        __half2* d = (__half2*)dst;
        d[2 * i    ] = __floats2half2_rn(v.x, v.y);
        d[2 * i + 1] = __floats2half2_rn(v.z, v.w);
    }
}

// ---------------- weight pack: [E][K][N] f32 -> k-pair-packed half -----------
// dst element layout (halves): e*K*N + (kp*N + n)*2 + (k&1),  kp = k/2
template<int K, int N>
__global__ void pack_weight_kernel(const float* __restrict__ W,
                                   __half* __restrict__ dst)
{
    const int per_e = (K / 2) * (N / 4);
    int i = blockIdx.x * blockDim.x + threadIdx.x;
    if (i >= NEXP * per_e) return;
    int e  = i / per_e;
    int r  = i % per_e;
    int kp = r / (N / 4);
    int n4 = (r % (N / 4)) * 4;

    const float* base = W + (size_t)e * K * N;
    float4 v0 = *(const float4*)(base + (size_t)(2 * kp    ) * N + n4);
    float4 v1 = *(const float4*)(base + (size_t)(2 * kp + 1) * N + n4);

    __half2* d = (__half2*)(dst + (size_t)e * K * N + ((size_t)kp * N + n4) * 2);
    d[0] = __floats2half2_rn(v0.x, v1.x);
    d[1] = __floats2half2_rn(v0.y, v1.y);
    d[2] = __floats2half2_rn(v0.z, v1.z);
    d[3] = __floats2half2_rn(v0.w, v1.w);
}

// ---------------- router: one warp per token --------------------------------
__global__ void router_kernel(const float* __restrict__ x,
                              const float* __restrict__ Wr,
                              const float* __restrict__ br)
{
    int warp = (blockIdx.x * blockDim.x + threadIdx.x) >> 5;
    int lane = threadIdx.x & 31;
    if (warp >= T_TOK) return;

    const float* xr = x + (size_t)warp * EMB;
    float acc[NEXP];
#pragma unroll
    for (int e = 0; e < NEXP; e++) acc[e] = 0.f;
    for (int i = lane; i < EMB; i += 32) {
        float xv = xr[i];
        const float* wrow = Wr + i * NEXP;
#pragma unroll
        for (int e = 0; e < NEXP; e++) acc[e] += xv * wrow[e];
    }
#pragma unroll
    for (int off = 16; off; off >>= 1)
#pragma unroll
        for (int e = 0; e < NEXP; e++)
            acc[e] += __shfl_xor_sync(0xffffffffu, acc[e], off);

    if (lane == 0) {
        float l[NEXP], p[NEXP];
        float mx = -1e30f;
#pragma unroll
        for (int e = 0; e < NEXP; e++) { l[e] = acc[e] + br[e]; mx = fmaxf(mx, l[e]); }
        float s = 0.f;
#pragma unroll
        for (int e = 0; e < NEXP; e++) { p[e] = expf(l[e] - mx); s += p[e]; }
        float inv = 1.f / s;

        int i1 = 0;
#pragma unroll
        for (int e = 1; e < NEXP; e++) if (p[e] > p[i1]) i1 = e;
        int i2 = (i1 == 0) ? 1 : 0;
#pragma unroll
        for (int e = 0; e < NEXP; e++) if (e != i1 && p[e] > p[i2]) i2 = e;

        int pos = atomicAdd(&g_counts[i1], 1);
        g_toks [i1 * CAP + pos] = warp;
        g_gates[i1 * CAP + pos] = p[i1] * inv;
        pos = atomicAdd(&g_counts[i2], 1);
        g_toks [i2 * CAP + pos] = warp;
        g_gates[i2 * CAP + pos] = p[i2] * inv;
    }
}

// ---------------- grouped FP16 tensor-core GEMM ------------------------------
// MODE 0: h1 = gather(x_h) @ W1[e] + b1[e]             -> fp16 store
// MODE 1: h2 = relu(h1 @ Wg[e] + bg[e])                -> fp16 store
// MODE 2: out[token] += gate * (h2 @ W2[e] + b2[e])    -> fp32 atomic scatter
template<int MODE, int N, int K>
__global__ __launch_bounds__(256, 1)
void mma_gemm_fp16(const __half* __restrict__ Aext,
                   const __half* __restrict__ B,
                   const float* __restrict__ bias,
                   float* __restrict__ out)
{
    const int e   = blockIdx.z;
    const int cnt = g_counts[e];
    const int m0  = blockIdx.y * BM;
    if (m0 >= cnt) return;
    const int n0  = blockIdx.x * BN;

    __shared__ __align__(16) __half As[2][BM][SA];   // 20480 B
    __shared__ __align__(16) __half Bs[2][16][SB];   // 17408 B

    const int tid  = threadIdx.x;
    const int lane = tid & 31;
    const int w    = tid >> 5;
    const int wm   = (w & 1) * 64;     // 2 warps in M
    const int wn   = (w >> 1) * 32;    // 4 warps in N
    const int gr   = lane >> 2;        // 0..7
    const int lc   = lane & 3;         // 0..3

    // ---- A cp.async: 4 x 16B per row, rows (tid>>2) and (tid>>2)+64 ----
    const int am = tid >> 2;           // 0..63
    const int ak = (tid & 3) * 8;      // half offset: 0,8,16,24
    const __half* arow0;
    const __half* arow1;
    if (MODE == 0) {
        int r0 = m0 + am;      r0 = r0 < cnt ? r0 : cnt - 1;
        int r1 = m0 + am + 64; r1 = r1 < cnt ? r1 : cnt - 1;
        arow0 = Aext + (size_t)g_toks[e * CAP + r0] * K + ak;
        arow1 = Aext + (size_t)g_toks[e * CAP + r1] * K + ak;
    } else {
        const __half* Ab = (MODE == 1) ? g_h1 : g_h2;
        arow0 = Ab + (size_t)(e * CAP + m0 + am) * K + ak;
        arow1 = arow0 + (size_t)64 * K;
    }
    // ---- B cp.async: packed rows (k-pairs), 2N halves per row ----
    const int bkp = tid >> 5;          // k-pair row 0..7 (and +8)
    const int bo  = (tid & 31) * 8;    // half offset within row
    const __half* bsrc = B + (size_t)e * K * N + (size_t)bkp * 2 * N
                           + (size_t)n0 * 2 + bo;

    const uint32_t sA0 = (uint32_t)__cvta_generic_to_shared(&As[0][am][ak]);
    const uint32_t sA1 = (uint32_t)__cvta_generic_to_shared(&As[0][am + 64][ak]);
    const uint32_t sB0 = (uint32_t)__cvta_generic_to_shared(&Bs[0][bkp][bo]);
    const uint32_t sB1 = (uint32_t)__cvta_generic_to_shared(&Bs[0][bkp + 8][bo]);
    const uint32_t aSz = sizeof(__half) * BM * SA;
    const uint32_t bSz = sizeof(__half) * 16 * SB;

    float acc[4][4][4];
#pragma unroll
    for (int i = 0; i < 4; i++)
#pragma unroll
        for (int j = 0; j < 4; j++)
#pragma unroll
            for (int q = 0; q < 4; q++) acc[i][j][q] = 0.f;

    auto load_stage = [&](int buf, int k0) {
        uint32_t ao = buf ? aSz : 0u, bof = buf ? bSz : 0u;
        cp16(sA0 + ao, arow0 + k0);
        cp16(sA1 + ao, arow1 + k0);
        // k-pair row k0/2 -> half offset (k0/2)*2N = k0*N ; +8 rows -> +16N
        cp16(sB0 + bof, bsrc + (size_t)k0 * N);
        cp16(sB1 + bof, bsrc + (size_t)k0 * N + (size_t)16 * N);
    };

    load_stage(0, 0);
    asm volatile("cp.async.commit_group;\n" ::: "memory");

    const int ITERS = K / BK;
    for (int it = 0; it < ITERS; it++) {
        if (it + 1 < ITERS) load_stage((it + 1) & 1, (it + 1) * BK);
        asm volatile("cp.async.commit_group;\n" ::: "memory");
        asm volatile("cp.async.wait_group 1;\n" ::: "memory");
        __syncthreads();
        const int b = it & 1;
#pragma unroll
        for (int kc = 0; kc < BK; kc += 16) {
            uint32_t af[4][4], bf[4][2];
#pragma unroll
            for (int i = 0; i < 4; i++) {
                int m = wm + i * 16 + gr;
                af[i][0] = *(const uint32_t*)&As[b][m    ][kc + 2 * lc];
                af[i][1] = *(const uint32_t*)&As[b][m + 8][kc + 2 * lc];
                af[i][2] = *(const uint32_t*)&As[b][m    ][kc + 2 * lc + 8];
                af[i][3] = *(const uint32_t*)&As[b][m + 8][kc + 2 * lc + 8];
            }
#pragma unroll
            for (int j = 0; j < 4; j++) {
                int n = wn + j * 8 + gr;
                bf[j][0] = *(const uint32_t*)&Bs[b][kc / 2 + lc    ][2 * n];
                bf[j][1] = *(const uint32_t*)&Bs[b][kc / 2 + lc + 4][2 * n];
            }
#pragma unroll
            for (int i = 0; i < 4; i++)
#pragma unroll
                for (int j = 0; j < 4; j++) {
                    asm volatile(
                        "mma.sync.aligned.m16n8k16.row.col.f32.f16.f16.f32 "
                        "{%0,%1,%2,%3}, {%4,%5,%6,%7}, {%8,%9}, {%0,%1,%2,%3};\n"
                        : "+f"(acc[i][j][0]), "+f"(acc[i][j][1]),
                          "+f"(acc[i][j][2]), "+f"(acc[i][j][3])
                        : "r"(af[i][0]), "r"(af[i][1]), "r"(af[i][2]), "r"(af[i][3]),
                          "r"(bf[j][0]), "r"(bf[j][1]));
                }
        }
        __syncthreads();
    }

    // ---------------- epilogue ----------------
    const float* bp = bias + (size_t)e * N;
    if (MODE == 2) {
#pragma unroll
        for (int i = 0; i < 4; i++)
#pragma unroll
            for (int half = 0; half < 2; half++) {
                int r = m0 + wm + i * 16 + gr + half * 8;
                if (r < cnt) {
                    int   tok = g_toks [e * CAP + r];
                    float gv  = g_gates[e * CAP + r];
#pragma unroll
                    for (int j = 0; j < 4; j++) {
                        int n = n0 + wn + j * 8 + lc * 2;
                        float v0 = acc[i][j][half * 2 + 0] + bp[n];
                        float v1 = acc[i][j][half * 2 + 1] + bp[n + 1];
                        atomicAdd(out + (size_t)tok * N + n,     gv * v0);
                        atomicAdd(out + (size_t)tok * N + n + 1, gv * v1);
                    }
                }
            }
    } else {
        __half* Cb = (MODE == 0) ? g_h1 : g_h2;
#pragma unroll
        for (int i = 0; i < 4; i++)
#pragma unroll
            for (int half = 0; half < 2; half++) {
                int r = m0 + wm + i * 16 + gr + half * 8;
                __half* crow = Cb + (size_t)(e * CAP + r) * N;
#pragma unroll
                for (int j = 0; j < 4; j++) {
                    int n = n0 + wn + j * 8 + lc * 2;
                    float v0 = acc[i][j][half * 2 + 0] + bp[n];
                    float v1 = acc[i][j][half * 2 + 1] + bp[n + 1];
                    if (MODE == 1) { v0 = fmaxf(v0, 0.f); v1 = fmaxf(v1, 0.f); }
                    *(__half2*)(crow + n) = __floats2half2_rn(v0, v1);
                }
            }
    }
}

// ---------------- launch -----------------------------------------------------
extern "C" void kernel_launch(void* const* d_in, const int* in_sizes, int n_in,
                              void* d_out, int out_size)
{
    const float* x  = (const float*)d_in[0];
    const float* Wr = (const float*)d_in[1];
    const float* br = (const float*)d_in[2];
    const float* W1 = (const float*)d_in[3];
    const float* b1 = (const float*)d_in[4];
    const float* Wg = (const float*)d_in[5];
    const float* bg = (const float*)d_in[6];
    const float* W2 = (const float*)d_in[7];
    const float* b2 = (const float*)d_in[8];
    float* out = (float*)d_out;

    __half *p_xh, *p_w1, *p_wg, *p_w2;
    cudaGetSymbolAddress((void**)&p_xh, g_xh);
    cudaGetSymbolAddress((void**)&p_w1, g_w1h);
    cudaGetSymbolAddress((void**)&p_wg, g_wgh);
    cudaGetSymbolAddress((void**)&p_w2, g_w2h);

    cudaMemsetAsync(out, 0, (size_t)T_TOK * EMB * sizeof(float));
    init_counts_kernel<<<1, 32>>>();
    router_kernel<<<(T_TOK * 32 + 255) / 256, 256>>>(x, Wr, br);

    {   // converts / packs
        int n4 = T_TOK * EMB / 4;
        xh_convert_kernel<<<(n4 + 255) / 256, 256>>>(x, p_xh, n4);
        int nt;
        nt = NEXP * (EMB / 2) * (HID / 4);
        pack_weight_kernel<EMB, HID><<<(nt + 255) / 256, 256>>>(W1, p_w1);
        nt = NEXP * (HID / 2) * (HID / 4);
        pack_weight_kernel<HID, HID><<<(nt + 255) / 256, 256>>>(Wg, p_wg);
        nt = NEXP * (HID / 2) * (EMB / 4);
        pack_weight_kernel<HID, EMB><<<(nt + 255) / 256, 256>>>(W2, p_w2);
    }

    dim3 blk(256);
    mma_gemm_fp16<0, HID, EMB><<<dim3(HID / BN, CAP / BM, NEXP), blk>>>(p_xh,    p_w1, b1, nullptr);
    mma_gemm_fp16<1, HID, HID><<<dim3(HID / BN, CAP / BM, NEXP), blk>>>(nullptr, p_wg, bg, nullptr);
    mma_gemm_fp16<2, EMB, HID><<<dim3(EMB / BN, CAP / BM, NEXP), blk>>>(nullptr, p_w2, b2, out);
}

// round 9
// speedup vs baseline: 6.5358x; 1.3024x over previous
#include <cuda_runtime.h>
#include <cuda_fp16.h>
#include <math.h>
#include <stdint.h>

#define T_TOK 4096
#define EMB   1024
#define NEXP  8
#define HID   2048
#define CAP   4096

#define BM 128
#define BN 128
#define BKH 64               // K halves per stage
#define SROW 72              // smem row stride in halves (144B: conflict-free)
#define ASTG (128 * SROW * 2)        // 18432 B per operand per stage
#define STGB (2 * ASTG)              // 36864 B per stage (A+B)
#define GSMEM (2 * STGB)             // 73728 B total (2 stages)

// ---------------- device scratch (no allocations allowed) -------------------
__device__ int    g_counts[NEXP];
__device__ int    g_toks [NEXP * CAP];
__device__ float  g_gates[NEXP * CAP];
__device__ __half g_act[(size_t)NEXP * CAP * EMB];   // gathered tokens fp16
__device__ __half g_h1 [(size_t)NEXP * CAP * HID];
__device__ __half g_h2 [(size_t)NEXP * CAP * HID];
__device__ __half g_w1t[(size_t)NEXP * HID * EMB];   // [E][N=HID][K=EMB]
__device__ __half g_wgt[(size_t)NEXP * HID * HID];   // [E][N=HID][K=HID]
__device__ __half g_w2t[(size_t)NEXP * EMB * HID];   // [E][N=EMB][K=HID]

// ---------------- helpers ----------------------------------------------------
__device__ __forceinline__ void cp16(uint32_t dst, const void* src) {
    asm volatile("cp.async.cg.shared.global [%0], [%1], 16;\n" :: "r"(dst), "l"(src));
}
__device__ __forceinline__ uint32_t smem_u32(const void* p) {
    return (uint32_t)__cvta_generic_to_shared(p);
}
__device__ __forceinline__ void ldsm4(uint32_t& r0, uint32_t& r1,
                                      uint32_t& r2, uint32_t& r3, uint32_t a) {
    asm volatile("ldmatrix.sync.aligned.m8n8.x4.shared.b16 {%0,%1,%2,%3}, [%4];"
                 : "=r"(r0), "=r"(r1), "=r"(r2), "=r"(r3) : "r"(a));
}

// ---------------- init ------------------------------------------------------
__global__ void init_counts_kernel() {
    if (threadIdx.x < NEXP) g_counts[threadIdx.x] = 0;
}

// ---------------- router: one warp per token --------------------------------
__global__ void router_kernel(const float* __restrict__ x,
                              const float* __restrict__ Wr,
                              const float* __restrict__ br)
{
    int warp = (blockIdx.x * blockDim.x + threadIdx.x) >> 5;
    int lane = threadIdx.x & 31;
    if (warp >= T_TOK) return;

    const float* xr = x + (size_t)warp * EMB;
    float acc[NEXP];
#pragma unroll
    for (int e = 0; e < NEXP; e++) acc[e] = 0.f;
    for (int i = lane; i < EMB; i += 32) {
        float xv = xr[i];
        const float* wrow = Wr + i * NEXP;
#pragma unroll
        for (int e = 0; e < NEXP; e++) acc[e] += xv * wrow[e];
    }
#pragma unroll
    for (int off = 16; off; off >>= 1)
#pragma unroll
        for (int e = 0; e < NEXP; e++)
            acc[e] += __shfl_xor_sync(0xffffffffu, acc[e], off);

    if (lane == 0) {
        float l[NEXP], p[NEXP];
        float mx = -1e30f;
#pragma unroll
        for (int e = 0; e < NEXP; e++) { l[e] = acc[e] + br[e]; mx = fmaxf(mx, l[e]); }
        float s = 0.f;
#pragma unroll
        for (int e = 0; e < NEXP; e++) { p[e] = expf(l[e] - mx); s += p[e]; }
        float inv = 1.f / s;

        int i1 = 0;
#pragma unroll
        for (int e = 1; e < NEXP; e++) if (p[e] > p[i1]) i1 = e;
        int i2 = (i1 == 0) ? 1 : 0;
#pragma unroll
        for (int e = 0; e < NEXP; e++) if (e != i1 && p[e] > p[i2]) i2 = e;

        int pos = atomicAdd(&g_counts[i1], 1);
        g_toks [i1 * CAP + pos] = warp;
        g_gates[i1 * CAP + pos] = p[i1] * inv;
        pos = atomicAdd(&g_counts[i2], 1);
        g_toks [i2 * CAP + pos] = warp;
        g_gates[i2 * CAP + pos] = p[i2] * inv;
    }
}

// ---------------- gather x rows -> fp16 activation buffer --------------------
__global__ void gather_kernel(const float* __restrict__ x)
{
    int b = blockIdx.x;             // row = e*CAP + i
    int e = b >> 12;
    int i = b & (CAP - 1);
    if (i >= g_counts[e]) return;
    int tok = g_toks[b];
    const float4* src = (const float4*)(x + (size_t)tok * EMB);
    __half2* dst = (__half2*)(g_act + (size_t)b * EMB);
    int t = threadIdx.x;            // 256 threads, EMB/4 = 256 float4
    float4 v = src[t];
    dst[2 * t    ] = __floats2half2_rn(v.x, v.y);
    dst[2 * t + 1] = __floats2half2_rn(v.z, v.w);
}

// ---------------- weight transpose-pack: [E][K][N] f32 -> [E][N][K] fp16 ----
// block: k-tile 64, n-tile 32; half2 stores (128B/warp)
template<int K, int N>
__global__ void pack_t_kernel(const float* __restrict__ W, __half* __restrict__ Wt)
{
    __shared__ float s[64][33];
    int e  = blockIdx.z;
    int k0 = blockIdx.x * 64;
    int n0 = blockIdx.y * 32;
    int tid = threadIdx.x;
    const float* src = W + (size_t)e * K * N;
#pragma unroll
    for (int i = 0; i < 8; i++) {
        int idx = tid + i * 256;
        int k = idx >> 5, n = idx & 31;
        s[k][n] = src[(size_t)(k0 + k) * N + n0 + n];
    }
    __syncthreads();
    __half2* dst = (__half2*)(Wt + (size_t)e * N * K);
#pragma unroll
    for (int i = 0; i < 4; i++) {
        int idx = tid + i * 256;        // 1024 half2: 32 n-rows x 32 half2
        int n = idx >> 5, j = idx & 31;
        dst[(size_t)(n0 + n) * (K / 2) + k0 / 2 + j] =
            __floats2half2_rn(s[2 * j][n], s[2 * j + 1][n]);
    }
}

// ---------------- grouped FP16 mma.sync GEMM with ldmatrix -------------------
// A: [rows][K] fp16 contiguous; B: [E][N][K] fp16 (K-major, transposed)
// MODE 0: h1 = A @ B^T + b1      MODE 1: h2 = relu(...)      MODE 2: scatter
template<int NOUT, int K, int MODE>
__global__ __launch_bounds__(256, 2)
void mma_gemm(const __half* __restrict__ A, const __half* __restrict__ B,
              const float* __restrict__ bias, float* __restrict__ out)
{
    const int e   = blockIdx.z;
    const int cnt = g_counts[e];
    const int m0  = blockIdx.y * BM;
    if (m0 >= cnt) return;
    const int n0  = blockIdx.x * BN;

    extern __shared__ __align__(16) char smem_raw[];
    const uint32_t sbase = smem_u32(smem_raw);

    const int tid  = threadIdx.x;
    const int lane = tid & 31;
    const int w    = tid >> 5;
    const int wm   = (w & 1) * 64;
    const int wn   = (w >> 1) * 32;
    const int gr   = lane >> 2;     // 0..7
    const int lc   = lane & 3;      // 0..3

    const __half* Abase = A + (size_t)(e * CAP + m0) * K;
    const __half* Bbase = B + ((size_t)e * NOUT + n0) * K;

    // cp.async: chunk g (0..1023 per operand): row=g>>3, 16B chunk c=g&7
    auto load_stage = [&](int j) {
        uint32_t sa = sbase + (j & 1) * STGB;
        uint32_t sb = sa + ASTG;
        const __half* ga = Abase + j * BKH;
        const __half* gb = Bbase + j * BKH;
#pragma unroll
        for (int i = 0; i < 4; i++) {
            int g   = tid + i * 256;
            int row = g >> 3, c = g & 7;
            uint32_t off = (uint32_t)(row * SROW + c * 8) * 2;
            cp16(sa + off, ga + (size_t)row * K + c * 8);
            cp16(sb + off, gb + (size_t)row * K + c * 8);
        }
    };

    // ldmatrix lane address components
    const int arow_l = ((lane >> 3) & 1) * 8 + (lane & 7);
    const int akoff  = (lane >> 4) * 8;
    const int brow_l = ((lane >> 4) & 1) * 8 + (lane & 7);
    const int bkoff  = ((lane >> 3) & 1) * 8;

    float acc[4][4][4];
#pragma unroll
    for (int i = 0; i < 4; i++)
#pragma unroll
        for (int j = 0; j < 4; j++)
#pragma unroll
            for (int q = 0; q < 4; q++) acc[i][j][q] = 0.f;

    load_stage(0);
    asm volatile("cp.async.commit_group;\n" ::: "memory");

    const int ITERS = K / BKH;
    for (int it = 0; it < ITERS; it++) {
        if (it + 1 < ITERS) load_stage(it + 1);
        asm volatile("cp.async.commit_group;\n" ::: "memory");
        asm volatile("cp.async.wait_group 1;\n" ::: "memory");
        __syncthreads();

        const uint32_t sa = sbase + (it & 1) * STGB;
        const uint32_t sb = sa + ASTG;
#pragma unroll
        for (int kc = 0; kc < BKH; kc += 16) {
            uint32_t af[4][4], bf[4][2];
#pragma unroll
            for (int i = 0; i < 4; i++) {
                uint32_t a = sa + (uint32_t)((wm + i * 16 + arow_l) * SROW + kc + akoff) * 2;
                ldsm4(af[i][0], af[i][1], af[i][2], af[i][3], a);
            }
            {
                uint32_t t0, t1, t2, t3;
                uint32_t a0 = sb + (uint32_t)((wn + brow_l) * SROW + kc + bkoff) * 2;
                ldsm4(t0, t1, t2, t3, a0);
                bf[0][0] = t0; bf[0][1] = t1; bf[1][0] = t2; bf[1][1] = t3;
                uint32_t a1 = sb + (uint32_t)((wn + 16 + brow_l) * SROW + kc + bkoff) * 2;
                ldsm4(t0, t1, t2, t3, a1);
                bf[2][0] = t0; bf[2][1] = t1; bf[3][0] = t2; bf[3][1] = t3;
            }
#pragma unroll
            for (int i = 0; i < 4; i++)
#pragma unroll
                for (int j = 0; j < 4; j++) {
                    asm volatile(
                        "mma.sync.aligned.m16n8k16.row.col.f32.f16.f16.f32 "
                        "{%0,%1,%2,%3}, {%4,%5,%6,%7}, {%8,%9}, {%0,%1,%2,%3};\n"
                        : "+f"(acc[i][j][0]), "+f"(acc[i][j][1]),
                          "+f"(acc[i][j][2]), "+f"(acc[i][j][3])
                        : "r"(af[i][0]), "r"(af[i][1]), "r"(af[i][2]), "r"(af[i][3]),
                          "r"(bf[j][0]), "r"(bf[j][1]));
                }
        }
        __syncthreads();
    }

    // ---------------- epilogue ----------------
    const float* bp = bias + (size_t)e * NOUT;
    if (MODE == 2) {
#pragma unroll
        for (int i = 0; i < 4; i++)
#pragma unroll
            for (int half = 0; half < 2; half++) {
                int r = m0 + wm + i * 16 + gr + half * 8;
                if (r < cnt) {
                    int   tok = g_toks [e * CAP + r];
                    float gv  = g_gates[e * CAP + r];
#pragma unroll
                    for (int j = 0; j < 4; j++) {
                        int n = n0 + wn + j * 8 + lc * 2;
                        float v0 = acc[i][j][half * 2 + 0] + bp[n];
                        float v1 = acc[i][j][half * 2 + 1] + bp[n + 1];
                        atomicAdd(out + (size_t)tok * NOUT + n,     gv * v0);
                        atomicAdd(out + (size_t)tok * NOUT + n + 1, gv * v1);
                    }
                }
            }
    } else {
        __half* Cb = (MODE == 0) ? g_h1 : g_h2;
#pragma unroll
        for (int i = 0; i < 4; i++)
#pragma unroll
            for (int half = 0; half < 2; half++) {
                int r = m0 + wm + i * 16 + gr + half * 8;
                __half* crow = Cb + (size_t)(e * CAP + r) * NOUT;
#pragma unroll
                for (int j = 0; j < 4; j++) {
                    int n = n0 + wn + j * 8 + lc * 2;
                    float v0 = acc[i][j][half * 2 + 0] + bp[n];
                    float v1 = acc[i][j][half * 2 + 1] + bp[n + 1];
                    if (MODE == 1) { v0 = fmaxf(v0, 0.f); v1 = fmaxf(v1, 0.f); }
                    *(__half2*)(crow + n) = __floats2half2_rn(v0, v1);
                }
            }
    }
}

// ---------------- launch -----------------------------------------------------
extern "C" void kernel_launch(void* const* d_in, const int* in_sizes, int n_in,
                              void* d_out, int out_size)
{
    const float* x  = (const float*)d_in[0];
    const float* Wr = (const float*)d_in[1];
    const float* br = (const float*)d_in[2];
    const float* W1 = (const float*)d_in[3];
    const float* b1 = (const float*)d_in[4];
    const float* Wg = (const float*)d_in[5];
    const float* bg = (const float*)d_in[6];
    const float* W2 = (const float*)d_in[7];
    const float* b2 = (const float*)d_in[8];
    float* out = (float*)d_out;

    __half *p_act, *p_w1, *p_wg, *p_w2, *p_h1, *p_h2;
    cudaGetSymbolAddress((void**)&p_act, g_act);
    cudaGetSymbolAddress((void**)&p_w1,  g_w1t);
    cudaGetSymbolAddress((void**)&p_wg,  g_wgt);
    cudaGetSymbolAddress((void**)&p_w2,  g_w2t);
    cudaGetSymbolAddress((void**)&p_h1,  g_h1);
    cudaGetSymbolAddress((void**)&p_h2,  g_h2);

    cudaFuncSetAttribute(mma_gemm<HID, EMB, 0>, cudaFuncAttributeMaxDynamicSharedMemorySize, GSMEM);
    cudaFuncSetAttribute(mma_gemm<HID, HID, 1>, cudaFuncAttributeMaxDynamicSharedMemorySize, GSMEM);
    cudaFuncSetAttribute(mma_gemm<EMB, HID, 2>, cudaFuncAttributeMaxDynamicSharedMemorySize, GSMEM);

    cudaMemsetAsync(out, 0, (size_t)T_TOK * EMB * sizeof(float));
    init_counts_kernel<<<1, 32>>>();
    router_kernel<<<(T_TOK * 32 + 255) / 256, 256>>>(x, Wr, br);
    gather_kernel<<<NEXP * CAP, 256>>>(x);

    pack_t_kernel<EMB, HID><<<dim3(EMB / 64, HID / 32, NEXP), 256>>>(W1, p_w1);
    pack_t_kernel<HID, HID><<<dim3(HID / 64, HID / 32, NEXP), 256>>>(Wg, p_wg);
    pack_t_kernel<HID, EMB><<<dim3(HID / 64, EMB / 32, NEXP), 256>>>(W2, p_w2);

    dim3 blk(256);
    mma_gemm<HID, EMB, 0><<<dim3(HID / BN, CAP / BM, NEXP), blk, GSMEM>>>(p_act, p_w1, b1, nullptr);
    mma_gemm<HID, HID, 1><<<dim3(HID / BN, CAP / BM, NEXP), blk, GSMEM>>>(p_h1,  p_wg, bg, nullptr);
    mma_gemm<EMB, HID, 2><<<dim3(EMB / BN, CAP / BM, NEXP), blk, GSMEM>>>(p_h2,  p_w2, b2, out);
}